// round 6
// baseline (speedup 1.0000x reference)
#include <cuda_runtime.h>
#include <cuda_fp16.h>
#include <cstdint>

// B=256, T=64 (K), S=16, U=4 -> P=256 pixels, O=1024 outputs/pixel.
//
// kernel 1: transpose+permute x (B,T,S,S) -> g_xA[p][...], fp16 pairs in exact
//           m16n8k16 A-fragment order (each thread's {a0..a3} = one LDS.128).
// kernel 2: CTA = (n-tile 16, m-tile 2, pixel 256), 128x64x64 GEMM via
//           mma.sync.m16n8k16.f32.f16.f16.f32, warp tile 32x32, 8 warps,
//           3 CTAs/SM. W converted fp32->fp16 during smem staging.
//           Epilogue adds bias (fp32) and scatters into pixel-shuffle layout.

__device__ uint32_t g_xA[256 * 8192];  // per pixel: 8192 uint32 = 16384 halves

__device__ __forceinline__ uint32_t smem_u32(const void* p) {
    uint32_t a;
    asm("{ .reg .u64 t; cvta.to.shared.u64 t, %1; cvt.u32.u64 %0, t; }" : "=r"(a) : "l"(p));
    return a;
}
__device__ __forceinline__ void cp16(uint32_t sdst, const void* g) {
    asm volatile("cp.async.cg.shared.global [%0], [%1], 16;" :: "r"(sdst), "l"(g));
}

// m16n8k16 A-fragment offset (uint32 units) for element pair (b, t even):
// mtile=b>>4, kstep=t>>4, g=b&7, hi8=(b>>3)&1, tt=t&15, pr=tt>>1, tig=pr&3,
// reg=hi8+2*(pr>>2), lane=g*4+tig.  off = mtile*512 + kstep*128 + lane*4 + reg
__device__ __forceinline__ int a_off_u32(int b, int t) {
    int g = b & 7, hi8 = (b >> 3) & 1;
    int pr = (t & 15) >> 1;
    int tig = pr & 3, reg = hi8 + ((pr >> 2) << 1);
    return ((b >> 4) << 9) + ((t >> 4) << 7) + ((g * 4 + tig) << 2) + reg;
}

// ---------------------------------------------------------------------------
// Transpose + permute + fp16 convert:
// x[b*16384 + t*256 + p] -> g_xA[p*8192 + a_off_u32(b,t)] (pairs over t)
// ---------------------------------------------------------------------------
__global__ void transpose_kernel(const float* __restrict__ x) {
    __shared__ float tile[32][33];
    int p0 = blockIdx.x * 32, t0 = blockIdx.y * 32, b = blockIdx.z;
    int tx = threadIdx.x, ty = threadIdx.y;
    int tid = ty * 32 + tx;
    const float* src = x + (size_t)b * 16384 + (size_t)t0 * 256 + p0;
#pragma unroll
    for (int k = 0; k < 4; k++) {
        int t = ty + k * 8;
        tile[t][tx] = src[t * 256 + tx];   // coalesced over p (=tx)
    }
    __syncthreads();
#pragma unroll
    for (int k = 0; k < 2; k++) {
        int idx = tid + k * 256;           // 512 (pixel, t-pair) items
        int pl = idx >> 4;                 // 0..31 pixel within tile
        int j  = idx & 15;                 // t-pair within tile
        int p = p0 + pl;
        int t = t0 + 2 * j;
        __half2 h = __floats2half2_rn(tile[2 * j][pl], tile[2 * j + 1][pl]);
        g_xA[(size_t)p * 8192 + a_off_u32(b, t)] = *(const uint32_t*)&h;
    }
}

// ---------------------------------------------------------------------------
// GEMM: C[128(b) x 64(o)] = A[128x64] @ W[64x64]^T + bias, per pixel.
// 256 threads = 8 warps (4m x 2n), warp tile 32x32, m16n8k16 f16.
// ---------------------------------------------------------------------------
#define AS_U32 4096   // 8 mtiles x 4 ksteps x 32 lanes x 4 regs
#define WS_U32 2048   // 8 ntiles x 4 ksteps x 32 lanes x 2 regs
#define SMEM_BYTES ((AS_U32 + WS_U32 + 64) * 4)

__global__ __launch_bounds__(256, 3) void gemm_kernel(const float* __restrict__ Wg_all,
                                                      const float* __restrict__ bias,
                                                      float* __restrict__ out) {
    extern __shared__ uint32_t smem[];
    uint32_t* As = smem;                  // [8 mtiles][4 ksteps][32][4]
    uint32_t* Ws = smem + AS_U32;         // [8 ntiles][4 ksteps][32][2]
    float* bias_s = (float*)(smem + AS_U32 + WS_U32);  // [64]

    const int bn = blockIdx.x;   // 0..15
    const int bm = blockIdx.y;   // 0..1
    const int p  = blockIdx.z;
    const int tid = threadIdx.x;
    const int lane = tid & 31, warp = tid >> 5;
    const int wm = warp >> 1, wn = warp & 1;   // 4m x 2n
    const int qr = lane >> 2, qc = lane & 3;

    // A: pre-permuted fp16; contiguous 16KB block per (p, bm)
    const uint32_t* Ag = g_xA + ((size_t)p << 13) + (bm << 12);
    uint32_t sA = smem_u32(As);
#pragma unroll
    for (int i = 0; i < 4; i++) {
        int idx = tid + i * 256;
        cp16(sA + idx * 16, Ag + idx * 4);
    }
    if (tid < 16) cp16(smem_u32(bias_s) + tid * 16, bias + (size_t)p * 1024 + bn * 64 + tid * 4);
    asm volatile("cp.async.commit_group;");

    // W: LDG.128 coalesced -> fp16 convert -> STS.32 x2 into fragment order
    const float* Wg = Wg_all + ((size_t)p << 16) + (size_t)(bn * 64) * 64;
#pragma unroll
    for (int i = 0; i < 4; i++) {
        int idx = tid + i * 256;          // 1024 float4s (64 o-rows x 16 f4/row)
        int r = idx >> 4;                 // o row 0..63
        int c = (idx & 15) << 2;          // t 0..60, %4==0
        float4 v = *(const float4*)(Wg + r * 64 + c);
        int g = r & 7;
        int pA = (c & 15) >> 1;           // even: 0,2,4,6
        int reg = pA >> 2;                // same for pA, pA+1
        int base = ((r >> 3) << 8) + ((c >> 4) << 6) + reg;
        __half2 h0 = __floats2half2_rn(v.x, v.y);
        __half2 h1 = __floats2half2_rn(v.z, v.w);
        Ws[base + ((g * 4 + (pA & 3)) << 1)]       = *(const uint32_t*)&h0;
        Ws[base + ((g * 4 + ((pA + 1) & 3)) << 1)] = *(const uint32_t*)&h1;
    }
    asm volatile("cp.async.wait_group 0;");
    __syncthreads();

    float acc[2][4][4];
#pragma unroll
    for (int mi = 0; mi < 2; mi++)
#pragma unroll
        for (int ni = 0; ni < 4; ni++)
#pragma unroll
            for (int q = 0; q < 4; q++) acc[mi][ni][q] = 0.f;

    const uint32_t* Abase = As + ((wm * 2) << 9) + lane * 4;   // + mi*512 + ks*128
    const uint32_t* Bbase = Ws + ((wn * 4) << 8) + lane * 2;   // + ni*256 + ks*64

#pragma unroll
    for (int ks = 0; ks < 4; ks++) {
        uint4 a[2];
        uint2 b[4];
#pragma unroll
        for (int mi = 0; mi < 2; mi++)
            a[mi] = *(const uint4*)(Abase + (mi << 9) + (ks << 7));
#pragma unroll
        for (int ni = 0; ni < 4; ni++)
            b[ni] = *(const uint2*)(Bbase + (ni << 8) + (ks << 6));
#pragma unroll
        for (int mi = 0; mi < 2; mi++)
#pragma unroll
            for (int ni = 0; ni < 4; ni++) {
                asm("mma.sync.aligned.m16n8k16.row.col.f32.f16.f16.f32 "
                    "{%0,%1,%2,%3}, {%4,%5,%6,%7}, {%8,%9}, {%0,%1,%2,%3};"
                    : "+f"(acc[mi][ni][0]), "+f"(acc[mi][ni][1]),
                      "+f"(acc[mi][ni][2]), "+f"(acc[mi][ni][3])
                    : "r"(a[mi].x), "r"(a[mi].y), "r"(a[mi].z), "r"(a[mi].w),
                      "r"(b[ni].x), "r"(b[ni].y));
            }
    }

    // Epilogue: o = bn*64 + o_loc; o viewed as (t, ui, uj); out is (256,64,64,64)
    const int i4 = (p >> 4) << 2, j4 = (p & 15) << 2;
#pragma unroll
    for (int ni = 0; ni < 4; ni++) {
        int o_loc = wn * 32 + ni * 8 + 2 * qc;
        int o = bn * 64 + o_loc;
        int t  = o >> 4;
        int ui = (o >> 2) & 3;
        int uj = o & 3;
        int coloff = t * 4096 + (i4 + ui) * 64 + j4 + uj;
        float b0 = bias_s[o_loc];
        float b1 = bias_s[o_loc + 1];
#pragma unroll
        for (int mi = 0; mi < 2; mi++) {
            int row = bm * 128 + wm * 32 + mi * 16 + qr;
            *(float2*)(out + (size_t)row * 262144 + coloff) =
                make_float2(acc[mi][ni][0] + b0, acc[mi][ni][1] + b1);
            *(float2*)(out + (size_t)(row + 8) * 262144 + coloff) =
                make_float2(acc[mi][ni][2] + b0, acc[mi][ni][3] + b1);
        }
    }
}

extern "C" void kernel_launch(void* const* d_in, const int* in_sizes, int n_in,
                              void* d_out, int out_size) {
    const float* x = (const float*)d_in[0];   // (256, 64, 16, 16)
    const float* W = (const float*)d_in[1];   // (256, 1024, 64)
    const float* b = (const float*)d_in[2];   // (256, 1024)
    float* out = (float*)d_out;               // (256, 64, 64, 64)
    (void)in_sizes; (void)n_in; (void)out_size;

    cudaFuncSetAttribute(gemm_kernel, cudaFuncAttributeMaxDynamicSharedMemorySize, SMEM_BYTES);

    transpose_kernel<<<dim3(8, 2, 256), dim3(32, 8)>>>(x);
    gemm_kernel<<<dim3(16, 2, 256), 256, SMEM_BYTES>>>(W, b, out);
}